// round 2
// baseline (speedup 1.0000x reference)
#include <cuda_runtime.h>
#include <cstdint>

// TDLoss: GAE backward scan over time + squared TD loss.
// Shapes: [T, B] time-major, T=256, B=65536.
// Inputs (metadata order): reward f32, step_type i32, discount f32, value f32, target_value f32.
// Output: loss f32 [T, B], with loss[T-1, :] = 0.

namespace {
constexpr int   T_STEPS = 256;
constexpr int   B_COLS  = 65536;
constexpr int   W       = B_COLS / 4;          // float4 columns = 16384
constexpr float GAMMA   = 0.99f;
constexpr float LAMBDA  = 0.95f;
constexpr int   STEP_TYPE_LAST = 2;
}

__global__ void __launch_bounds__(64, 2)
td_loss_kernel(const float4* __restrict__ reward,
               const int4*   __restrict__ step_type,
               const float4* __restrict__ discount,
               const float4* __restrict__ value,
               const float4* __restrict__ tv,
               float4*       __restrict__ out)
{
    const int c = blockIdx.x * blockDim.x + threadIdx.x;   // 0 .. W-1
    if (c >= W) return;

    // Zero the last time row (output is poisoned by the harness).
    out[(T_STEPS - 1) * W + c] = make_float4(0.f, 0.f, 0.f, 0.f);

    float4 adv = make_float4(0.f, 0.f, 0.f, 0.f);
    float4 tvn = tv[(T_STEPS - 1) * W + c];                // target_value[t+1] carry

    #pragma unroll 5
    for (int t = T_STEPS - 2; t >= 0; --t) {
        const int i1 = (t + 1) * W + c;
        const int i0 = t * W + c;

        // 5 independent 16B loads — address-only dependent, batched by ptxas.
        const float4 r   = reward[i1];
        const float4 d   = discount[i1];
        const float4 tvc = tv[i0];
        const int4   st  = step_type[i0];
        const float4 v   = value[i0];

        float4 o;

        // Per-lane GAE step:
        //   disc  = discount[t+1] * GAMMA
        //   delta = reward[t+1] + disc*tv[t+1] - tv[t]
        //   adv   = is_last(t) ? 0 : delta + disc*LAMBDA*adv
        //   loss  = (value[t] - (adv + tv[t]))^2
        #define LANE(X)                                                     \
        {                                                                   \
            const float disc  = d.X * GAMMA;                                \
            const float delta = fmaf(disc, tvn.X, r.X) - tvc.X;             \
            const float wd    = disc * LAMBDA;                              \
            float a           = fmaf(wd, adv.X, delta);                     \
            a                 = (st.X == STEP_TYPE_LAST) ? 0.f : a;         \
            adv.X             = a;                                          \
            const float diff  = v.X - (a + tvc.X);                         \
            o.X               = diff * diff;                                \
        }
        LANE(x) LANE(y) LANE(z) LANE(w)
        #undef LANE

        out[i0] = o;
        tvn = tvc;
    }
}

extern "C" void kernel_launch(void* const* d_in, const int* in_sizes, int n_in,
                              void* d_out, int out_size)
{
    const float4* reward    = (const float4*)d_in[0];
    const int4*   step_type = (const int4*)  d_in[1];
    const float4* discount  = (const float4*)d_in[2];
    const float4* value     = (const float4*)d_in[3];
    const float4* tv        = (const float4*)d_in[4];
    float4*       out       = (float4*)d_out;

    const int threads = 64;
    const int blocks  = W / threads;  // 16384 / 64 = 256
    td_loss_kernel<<<blocks, threads>>>(reward, step_type, discount, value, tv, out);
}

// round 4
// speedup vs baseline: 1.0683x; 1.0683x over previous
#include <cuda_runtime.h>
#include <cstdint>

// TDLoss: GAE backward scan over time + squared TD loss.
// Shapes: [T, B] time-major, T=256, B=65536.
// Inputs (metadata order): reward f32, step_type i32, discount f32, value f32, target_value f32.
// Output: loss f32 [T, B], with loss[T-1, :] = 0.
//
// R4 (= R3 resubmit; infra ate R3): float2 lanes, 32768 threads (512 x 64)
// to double occupancy and cut register pressure so the unroll-5 load batch
// actually stays in flight.

namespace {
constexpr int   T_STEPS = 256;
constexpr int   B_COLS  = 65536;
constexpr int   W2      = B_COLS / 2;          // float2 columns = 32768
constexpr float GAMMA   = 0.99f;
constexpr float LAMBDA  = 0.95f;
constexpr int   STEP_TYPE_LAST = 2;
}

__global__ void __launch_bounds__(64, 8)
td_loss_kernel(const float2* __restrict__ reward,
               const int2*   __restrict__ step_type,
               const float2* __restrict__ discount,
               const float2* __restrict__ value,
               const float2* __restrict__ tv,
               float2*       __restrict__ out)
{
    const int c = blockIdx.x * blockDim.x + threadIdx.x;   // 0 .. W2-1

    // Zero the last time row (output is poisoned by the harness).
    out[(T_STEPS - 1) * W2 + c] = make_float2(0.f, 0.f);

    float2 adv = make_float2(0.f, 0.f);
    float2 tvn = tv[(T_STEPS - 1) * W2 + c];               // target_value[t+1] carry

    #pragma unroll 5
    for (int t = T_STEPS - 2; t >= 0; --t) {
        const int i1 = (t + 1) * W2 + c;
        const int i0 = t * W2 + c;

        // 5 independent loads — address-only dependent, batched by ptxas.
        const float2 r   = reward[i1];
        const float2 d   = discount[i1];
        const float2 tvc = tv[i0];
        const int2   st  = step_type[i0];
        const float2 v   = value[i0];

        float2 o;

        // Per-lane GAE step:
        //   disc  = discount[t+1] * GAMMA
        //   delta = reward[t+1] + disc*tv[t+1] - tv[t]
        //   adv   = is_last(t) ? 0 : delta + disc*LAMBDA*adv
        //   loss  = (value[t] - (adv + tv[t]))^2
        #define LANE(X)                                                     \
        {                                                                   \
            const float disc  = d.X * GAMMA;                                \
            const float delta = fmaf(disc, tvn.X, r.X) - tvc.X;             \
            const float wd    = disc * LAMBDA;                              \
            float a           = fmaf(wd, adv.X, delta);                     \
            a                 = (st.X == STEP_TYPE_LAST) ? 0.f : a;         \
            adv.X             = a;                                          \
            const float diff  = v.X - (a + tvc.X);                          \
            o.X               = diff * diff;                                \
        }
        LANE(x) LANE(y)
        #undef LANE

        out[i0] = o;
        tvn = tvc;
    }
}

extern "C" void kernel_launch(void* const* d_in, const int* in_sizes, int n_in,
                              void* d_out, int out_size)
{
    const float2* reward    = (const float2*)d_in[0];
    const int2*   step_type = (const int2*)  d_in[1];
    const float2* discount  = (const float2*)d_in[2];
    const float2* value     = (const float2*)d_in[3];
    const float2* tv        = (const float2*)d_in[4];
    float2*       out       = (float2*)d_out;

    const int threads = 64;
    const int blocks  = W2 / threads;  // 32768 / 64 = 512
    td_loss_kernel<<<blocks, threads>>>(reward, step_type, discount, value, tv, out);
}